// round 1
// baseline (speedup 1.0000x reference)
#include <cuda_runtime.h>
#include <cstdint>

#define Bb     2
#define LL     2048
#define DM     512
#define ED_    1024
#define NS     16
#define DTR    32
#define DFF    1024
#define BLr    (Bb*LL)            /* 4096 rows */

/* ------------------------------------------------------------------ */
/* scratch (__device__ globals: no allocation allowed)                  */
/* ------------------------------------------------------------------ */
__device__ float g_xb   [BLr*DM];          /* flipped x                */
__device__ float g_xz   [BLr*2*ED_];       /* xs | z                   */
__device__ float g_xc   [BLr*ED_];         /* conv+silu output         */
__device__ float g_dbl  [BLr*64];          /* dt(32) Bm(16) C(16)      */
__device__ float g_delta[BLr*ED_];
__device__ float g_y    [BLr*ED_];         /* scan out * silu(z)       */
__device__ float g_U    [2*BLr*DM];        /* ffn input (fwd LN / bwd) */
__device__ float g_Vh   [2*BLr*DFF];       /* ffn hidden               */
__device__ float g_V2   [2*BLr*DM];        /* ffn output               */

/* ------------------------------------------------------------------ */
__device__ __forceinline__ float softplusf(float x) {
    return fmaxf(x, 0.f) + log1pf(expf(-fabsf(x)));
}
__device__ __forceinline__ float siluf(float x) {
    return x / (1.f + __expf(-x));
}

/* ------------------------------------------------------------------ */
/* generic fp32 tiled GEMM: C[M,N] = A[M,K](lda) @ B[K,N], epilogue     */
/* ep: 0 none, 1 bias+relu, 2 bias, 3 softplus(bias+x)                  */
/* requires M%64==0, N%64==0, K%16==0                                   */
/* ------------------------------------------------------------------ */
__global__ __launch_bounds__(256)
void gemm_kernel(const float* __restrict__ A, int lda,
                 const float* __restrict__ B, int N, int K,
                 float* __restrict__ C,
                 const float* __restrict__ bias, int ep)
{
    __shared__ float As[16][68];
    __shared__ float Bs[16][68];

    const int tid  = threadIdx.x;
    const int tx   = tid & 15;      /* n-dir 0..15 */
    const int ty   = tid >> 4;      /* m-dir 0..15 */
    const int row0 = blockIdx.y * 64;
    const int col0 = blockIdx.x * 64;

    const int ar = tid >> 2;            /* 0..63 */
    const int ak = (tid & 3) << 2;      /* 0,4,8,12 */
    const int bk = tid >> 4;            /* 0..15 */
    const int bn = (tid & 15) << 2;     /* 0..60 */

    float acc[4][4];
#pragma unroll
    for (int i = 0; i < 4; ++i)
#pragma unroll
        for (int j = 0; j < 4; ++j) acc[i][j] = 0.f;

    for (int k0 = 0; k0 < K; k0 += 16) {
        float4 av = *(const float4*)(A + (size_t)(row0 + ar) * lda + k0 + ak);
        As[ak + 0][ar] = av.x;
        As[ak + 1][ar] = av.y;
        As[ak + 2][ar] = av.z;
        As[ak + 3][ar] = av.w;
        *(float4*)&Bs[bk][bn] =
            *(const float4*)(B + (size_t)(k0 + bk) * N + col0 + bn);
        __syncthreads();

#pragma unroll
        for (int kk = 0; kk < 16; ++kk) {
            float4 a = *(const float4*)&As[kk][ty << 2];
            float4 b = *(const float4*)&Bs[kk][tx << 2];
            float ai[4] = {a.x, a.y, a.z, a.w};
            float bj[4] = {b.x, b.y, b.z, b.w};
#pragma unroll
            for (int i = 0; i < 4; ++i)
#pragma unroll
                for (int j = 0; j < 4; ++j)
                    acc[i][j] = fmaf(ai[i], bj[j], acc[i][j]);
        }
        __syncthreads();
    }

    const int m0 = row0 + (ty << 2);
    const int n0 = col0 + (tx << 2);
    float4 bv = make_float4(0.f, 0.f, 0.f, 0.f);
    if (ep) bv = *(const float4*)(bias + n0);

#pragma unroll
    for (int i = 0; i < 4; ++i) {
        float4 o = make_float4(acc[i][0], acc[i][1], acc[i][2], acc[i][3]);
        if (ep == 1) {
            o.x = fmaxf(o.x + bv.x, 0.f); o.y = fmaxf(o.y + bv.y, 0.f);
            o.z = fmaxf(o.z + bv.z, 0.f); o.w = fmaxf(o.w + bv.w, 0.f);
        } else if (ep == 2) {
            o.x += bv.x; o.y += bv.y; o.z += bv.z; o.w += bv.w;
        } else if (ep == 3) {
            o.x = softplusf(o.x + bv.x); o.y = softplusf(o.y + bv.y);
            o.z = softplusf(o.z + bv.z); o.w = softplusf(o.w + bv.w);
        }
        *(float4*)(C + (size_t)(m0 + i) * N + n0) = o;
    }
}

/* ------------------------------------------------------------------ */
/* flip along L (per batch), vectorized float4                         */
/* ------------------------------------------------------------------ */
__global__ void flip_kernel(const float* __restrict__ x, float* __restrict__ xb)
{
    int idx = blockIdx.x * 256 + threadIdx.x;          /* < BLr*DM/4 */
    int c = idx & 127;                                 /* DM/4 = 128 */
    int r = idx >> 7;
    int b = r >> 11;
    int l = r & 2047;
    ((float4*)xb)[idx] =
        ((const float4*)x)[(size_t)(((b << 11) + (2047 - l)) << 7) + c];
}

/* ------------------------------------------------------------------ */
/* depthwise causal conv (K=4) + bias + silu                           */
/* ------------------------------------------------------------------ */
__global__ void conv_silu_kernel(const float* __restrict__ xz,
                                 const float* __restrict__ cw,
                                 const float* __restrict__ cb,
                                 float* __restrict__ xc)
{
    int idx = blockIdx.x * blockDim.x + threadIdx.x;   /* < BLr*ED_ */
    int e = idx & 1023;
    int r = idx >> 10;
    int l = r & 2047;
    int b = r >> 11;
    float s = cb[e];
#pragma unroll
    for (int k = 0; k < 4; ++k) {
        int ll = l + k - 3;
        if (ll >= 0)
            s = fmaf(xz[((size_t)((b << 11) + ll) << 11) + e], cw[(e << 2) + k], s);
    }
    xc[idx] = siluf(s);
}

/* ------------------------------------------------------------------ */
/* selective scan: 16 N-states -> 16 lanes, 2 chains per warp          */
/* fused: y = (scan + xc*D) * silu(z)                                  */
/* ------------------------------------------------------------------ */
__global__ __launch_bounds__(256)
void scan_kernel(const float* __restrict__ delta, const float* __restrict__ xc,
                 const float* __restrict__ dbl,   const float* __restrict__ xz,
                 const float* __restrict__ A_log, const float* __restrict__ Dp,
                 float* __restrict__ y)
{
    int warp  = (blockIdx.x * blockDim.x + threadIdx.x) >> 5;
    int lane  = threadIdx.x & 31;
    int half  = lane >> 4;
    int n     = lane & 15;
    int chain = (warp << 1) + half;       /* 0..2047 */
    int b = chain >> 10;
    int e = chain & 1023;

    const float a  = -expf(A_log[(e << 4) + n]);
    const float dc = Dp[e];
    float h = 0.f;
    const int rowbase = b << 11;

    for (int l = 0; l < LL; ++l) {
        const int row = rowbase + l;
        float d  = __ldg(&delta[(size_t)(row << 10) + e]);
        float xv = __ldg(&xc   [(size_t)(row << 10) + e]);
        float bv = __ldg(&dbl  [(row << 6) + 32 + n]);
        float cv = __ldg(&dbl  [(row << 6) + 48 + n]);
        float dA = __expf(d * a);
        h = fmaf(dA, h, d * xv * bv);
        float p = h * cv;
        p += __shfl_xor_sync(0xffffffffu, p, 1);
        p += __shfl_xor_sync(0xffffffffu, p, 2);
        p += __shfl_xor_sync(0xffffffffu, p, 4);
        p += __shfl_xor_sync(0xffffffffu, p, 8);
        if (n == 0) {
            float zv = xz[((size_t)row << 11) + 1024 + e];
            y[(size_t)(row << 10) + e] = (p + xv * dc) * siluf(zv);
        }
    }
}

/* ------------------------------------------------------------------ */
/* layernorm in place over 512 cols (two-pass, exact var)              */
/* ------------------------------------------------------------------ */
__global__ __launch_bounds__(128)
void ln_kernel(float* __restrict__ U, const float* __restrict__ g,
               const float* __restrict__ bb)
{
    int row = blockIdx.x;
    float4* p = (float4*)(U + (size_t)row * DM);
    int tid = threadIdx.x;                 /* 128 */
    int lane = tid & 31, w = tid >> 5;
    __shared__ float red[4];

    float4 v = p[tid];
    float s = v.x + v.y + v.z + v.w;
#pragma unroll
    for (int o = 16; o; o >>= 1) s += __shfl_xor_sync(0xffffffffu, s, o);
    if (!lane) red[w] = s;
    __syncthreads();
    float mu = (red[0] + red[1] + red[2] + red[3]) * (1.f / 512.f);

    float dx = v.x - mu, dy = v.y - mu, dz = v.z - mu, dw = v.w - mu;
    float s2 = dx*dx + dy*dy + dz*dz + dw*dw;
#pragma unroll
    for (int o = 16; o; o >>= 1) s2 += __shfl_xor_sync(0xffffffffu, s2, o);
    __syncthreads();
    if (!lane) red[w] = s2;
    __syncthreads();
    float var  = (red[0] + red[1] + red[2] + red[3]) * (1.f / 512.f);
    float rstd = rsqrtf(var + 1e-5f);

    int c = tid << 2;
    float4 go = *(const float4*)(g + c);
    float4 bo = *(const float4*)(bb + c);
    float4 o;
    o.x = dx * rstd * go.x + bo.x;
    o.y = dy * rstd * go.y + bo.y;
    o.z = dz * rstd * go.z + bo.z;
    o.w = dw * rstd * go.w + bo.w;
    p[tid] = o;
}

/* ------------------------------------------------------------------ */
/* final: out = V2_f + V2_b + U_f + U_b                                 */
/* ------------------------------------------------------------------ */
__global__ void final_kernel(const float* __restrict__ V2,
                             const float* __restrict__ U,
                             float* __restrict__ out)
{
    int idx = blockIdx.x * 256 + threadIdx.x;          /* < BLr*DM/4 */
    const int off = (BLr * DM) >> 2;
    float4 a = ((const float4*)V2)[idx];
    float4 b = ((const float4*)V2)[idx + off];
    float4 c = ((const float4*)U)[idx];
    float4 d = ((const float4*)U)[idx + off];
    float4 o;
    o.x = a.x + b.x + c.x + d.x;
    o.y = a.y + b.y + c.y + d.y;
    o.z = a.z + b.z + c.z + d.z;
    o.w = a.w + b.w + c.w + d.w;
    ((float4*)out)[idx] = o;
}

/* ------------------------------------------------------------------ */
extern "C" void kernel_launch(void* const* d_in, const int* in_sizes, int n_in,
                              void* d_out, int out_size)
{
    (void)in_sizes; (void)n_in; (void)out_size;

    float *xb, *xz, *xc, *dbl, *delta, *y, *U, *Vh, *V2;
    cudaGetSymbolAddress((void**)&xb,    g_xb);
    cudaGetSymbolAddress((void**)&xz,    g_xz);
    cudaGetSymbolAddress((void**)&xc,    g_xc);
    cudaGetSymbolAddress((void**)&dbl,   g_dbl);
    cudaGetSymbolAddress((void**)&delta, g_delta);
    cudaGetSymbolAddress((void**)&y,     g_y);
    cudaGetSymbolAddress((void**)&U,     g_U);
    cudaGetSymbolAddress((void**)&Vh,    g_Vh);
    cudaGetSymbolAddress((void**)&V2,    g_V2);

    const float* x = (const float*)d_in[0];
    const float* norm1_g = (const float*)d_in[19];
    const float* norm1_b = (const float*)d_in[20];
    const float* ffn_w1  = (const float*)d_in[23];
    const float* ffn_b1  = (const float*)d_in[24];
    const float* ffn_w2  = (const float*)d_in[25];
    const float* ffn_b2  = (const float*)d_in[26];

    for (int dir = 0; dir < 2; ++dir) {
        const float* in_w    = (const float*)d_in[1 + dir * 9 + 0];
        const float* conv_w  = (const float*)d_in[1 + dir * 9 + 1];
        const float* conv_b  = (const float*)d_in[1 + dir * 9 + 2];
        const float* xproj_w = (const float*)d_in[1 + dir * 9 + 3];
        const float* dt_w    = (const float*)d_in[1 + dir * 9 + 4];
        const float* dt_b    = (const float*)d_in[1 + dir * 9 + 5];
        const float* A_log   = (const float*)d_in[1 + dir * 9 + 6];
        const float* Dv      = (const float*)d_in[1 + dir * 9 + 7];
        const float* out_w   = (const float*)d_in[1 + dir * 9 + 8];

        const float* Asrc = x;
        if (dir == 1) {
            flip_kernel<<<(BLr * DM / 4) / 256, 256>>>(x, xb);
            Asrc = xb;
        }

        /* xz = x @ in_w : 4096 x 2048 x 512 */
        gemm_kernel<<<dim3(2 * ED_ / 64, BLr / 64), 256>>>(
            Asrc, DM, in_w, 2 * ED_, DM, xz, nullptr, 0);

        /* depthwise conv + silu */
        conv_silu_kernel<<<(BLr * ED_) / 256, 256>>>(xz, conv_w, conv_b, xc);

        /* dbl = xc @ xproj_w : 4096 x 64 x 1024 */
        gemm_kernel<<<dim3(64 / 64, BLr / 64), 256>>>(
            xc, ED_, xproj_w, 64, ED_, dbl, nullptr, 0);

        /* delta = softplus(dt @ dt_w + dt_b) : 4096 x 1024 x 32, lda=64 */
        gemm_kernel<<<dim3(ED_ / 64, BLr / 64), 256>>>(
            dbl, 64, dt_w, ED_, DTR, delta, dt_b, 3);

        /* selective scan, fused with silu(z) gate */
        scan_kernel<<<128, 256>>>(delta, xc, dbl, xz, A_log, Dv, y);

        /* m = y @ out_w : 4096 x 512 x 1024  -> U[dir] */
        gemm_kernel<<<dim3(DM / 64, BLr / 64), 256>>>(
            y, ED_, out_w, DM, ED_, U + (size_t)dir * BLr * DM, nullptr, 0);

        if (dir == 0)
            ln_kernel<<<BLr, 128>>>(U, norm1_g, norm1_b);
    }

    /* FFN over both directions batched: 8192 rows */
    gemm_kernel<<<dim3(DFF / 64, 2 * BLr / 64), 256>>>(
        U, DM, ffn_w1, DFF, DM, Vh, ffn_b1, 1);
    gemm_kernel<<<dim3(DM / 64, 2 * BLr / 64), 256>>>(
        Vh, DFF, ffn_w2, DM, DFF, V2, ffn_b2, 2);

    final_kernel<<<(BLr * DM / 4) / 256, 256>>>(V2, U, (float*)d_out);
}

// round 3
// speedup vs baseline: 1.5783x; 1.5783x over previous
#include <cuda_runtime.h>
#include <cuda_bf16.h>
#include <cstdint>

#define Bb     2
#define LL     2048
#define DM     512
#define ED_    1024
#define NS     16
#define DTR    32
#define DFF    1024
#define BLr    (Bb*LL)            /* 4096 rows */

/* ------------------------------------------------------------------ */
/* scratch                                                             */
/* ------------------------------------------------------------------ */
__device__ float g_xb   [BLr*DM];
__device__ float g_xz   [BLr*2*ED_];
__device__ float g_xc   [BLr*ED_];
__device__ float g_dbl  [BLr*64];
__device__ float g_delta[BLr*ED_];
__device__ float g_y    [BLr*ED_];
__device__ float g_U    [2*BLr*DM];
__device__ float g_Vh   [2*BLr*DFF];
__device__ float g_V2   [2*BLr*DM];

/* bf16 hi/lo staging for MMA GEMMs */
__device__ __nv_bfloat16 g_Ahi[2*BLr*ED_];
__device__ __nv_bfloat16 g_Alo[2*BLr*ED_];
__device__ __nv_bfloat16 g_Bhi[2*1024*1024];
__device__ __nv_bfloat16 g_Blo[2*1024*1024];

/* ------------------------------------------------------------------ */
__device__ __forceinline__ float softplusf(float x) {
    return fmaxf(x, 0.f) + log1pf(expf(-fabsf(x)));
}
__device__ __forceinline__ float siluf(float x) {
    return x / (1.f + __expf(-x));
}
__device__ __forceinline__ uint32_t smem_u32(const void* p) {
    uint32_t a;
    asm("{ .reg .u64 t; cvta.to.shared.u64 t, %1; cvt.u32.u64 %0, t; }"
        : "=r"(a) : "l"(p));
    return a;
}

/* ================= HMMA helpers =================================== */
__device__ __forceinline__ void ldm_x4(uint32_t* r, uint32_t addr) {
    asm volatile("ldmatrix.sync.aligned.m8n8.x4.shared.b16 {%0,%1,%2,%3}, [%4];"
                 : "=r"(r[0]), "=r"(r[1]), "=r"(r[2]), "=r"(r[3]) : "r"(addr));
}
__device__ __forceinline__ void ldm_x4t(uint32_t* r, uint32_t addr) {
    asm volatile("ldmatrix.sync.aligned.m8n8.x4.trans.shared.b16 {%0,%1,%2,%3}, [%4];"
                 : "=r"(r[0]), "=r"(r[1]), "=r"(r[2]), "=r"(r[3]) : "r"(addr));
}
__device__ __forceinline__ void mma_bf16(float* c, const uint32_t* a,
                                         const uint32_t* b) {
    asm volatile(
        "mma.sync.aligned.m16n8k16.row.col.f32.bf16.bf16.f32 "
        "{%0,%1,%2,%3},{%4,%5,%6,%7},{%8,%9},{%0,%1,%2,%3};"
        : "+f"(c[0]), "+f"(c[1]), "+f"(c[2]), "+f"(c[3])
        : "r"(a[0]), "r"(a[1]), "r"(a[2]), "r"(a[3]), "r"(b[0]), "r"(b[1]));
}

/* ================= fp32 -> bf16 hi/lo convert ===================== */
__global__ void cvt_kernel(const float* __restrict__ s,
                           __nv_bfloat16* __restrict__ hi,
                           __nv_bfloat16* __restrict__ lo, int n4)
{
    int i = blockIdx.x * 256 + threadIdx.x;
    if (i >= n4) return;
    float4 v = ((const float4*)s)[i];
    __nv_bfloat162 h01 = __floats2bfloat162_rn(v.x, v.y);
    float2 f01 = __bfloat1622float2(h01);
    __nv_bfloat162 l01 = __floats2bfloat162_rn(v.x - f01.x, v.y - f01.y);
    __nv_bfloat162 h23 = __floats2bfloat162_rn(v.z, v.w);
    float2 f23 = __bfloat1622float2(h23);
    __nv_bfloat162 l23 = __floats2bfloat162_rn(v.z - f23.x, v.w - f23.y);
    ((__nv_bfloat162*)hi)[i * 2]     = h01;
    ((__nv_bfloat162*)hi)[i * 2 + 1] = h23;
    ((__nv_bfloat162*)lo)[i * 2]     = l01;
    ((__nv_bfloat162*)lo)[i * 2 + 1] = l23;
}

/* ================= split-bf16 HMMA GEMM =========================== */
/* C[M,N] = A[M,K] @ B[K,N], A/B pre-split bf16 hi/lo.                */
/* 128x128x32 tiles, 8 warps, each 64x32. ep: 0 none, 1 b+relu, 2 b.  */

#define OFF_ALO 10240
#define OFF_BHI 20480
#define OFF_BLO 29184
#define BUFSZ   37888
#define MM_SMEM (2*BUFSZ)

__global__ void __launch_bounds__(256, 1)
mma_gemm(const __nv_bfloat16* __restrict__ Ahi,
         const __nv_bfloat16* __restrict__ Alo,
         const __nv_bfloat16* __restrict__ Bhi,
         const __nv_bfloat16* __restrict__ Blo,
         int N, int K, float* __restrict__ C,
         const float* __restrict__ bias, int ep)
{
    extern __shared__ char sm[];
    const uint32_t sb = smem_u32(sm);
    const int tid  = threadIdx.x;
    const int lane = tid & 31;
    const int wid  = tid >> 5;
    const int wm   = wid & 1;       /* 0..1: 64-row half       */
    const int wn   = wid >> 1;      /* 0..3: 32-col strip      */
    const int m0 = blockIdx.y * 128;
    const int n0 = blockIdx.x * 128;

    /* per-thread tile-load coordinates */
    const int a_row = tid >> 2;     /* 0..63 (and +64)  */
    const int a_ch  = tid & 3;      /* 16B chunk in 64B row */
    const int b_row = tid >> 4;     /* 0..15 (and +16)  */
    const int b_ch  = tid & 15;     /* 16B chunk in 256B row */

    const __nv_bfloat16* gA0h = Ahi + (size_t)(m0 + a_row) * K + a_ch * 8;
    const __nv_bfloat16* gA1h = gA0h + (size_t)64 * K;
    const __nv_bfloat16* gA0l = Alo + (size_t)(m0 + a_row) * K + a_ch * 8;
    const __nv_bfloat16* gA1l = gA0l + (size_t)64 * K;
    const __nv_bfloat16* gB0h = Bhi + (size_t)b_row * N + n0 + b_ch * 8;
    const __nv_bfloat16* gB1h = gB0h + (size_t)16 * N;
    const __nv_bfloat16* gB0l = Blo + (size_t)b_row * N + n0 + b_ch * 8;
    const __nv_bfloat16* gB1l = gB0l + (size_t)16 * N;

    const int sa0 = a_row * 80 + a_ch * 16;
    const int sa1 = (a_row + 64) * 80 + a_ch * 16;
    const int sb0 = b_row * 272 + b_ch * 16;
    const int sb1 = (b_row + 16) * 272 + b_ch * 16;

    float acc[4][4][4];
#pragma unroll
    for (int i = 0; i < 4; ++i)
#pragma unroll
        for (int j = 0; j < 4; ++j)
#pragma unroll
            for (int q = 0; q < 4; ++q) acc[i][j][q] = 0.f;

    uint4 ra0h, ra1h, ra0l, ra1l, rb0h, rb1h, rb0l, rb1l;

    /* preload tile 0 */
    ra0h = *(const uint4*)gA0h;  ra1h = *(const uint4*)gA1h;
    ra0l = *(const uint4*)gA0l;  ra1l = *(const uint4*)gA1l;
    rb0h = *(const uint4*)gB0h;  rb1h = *(const uint4*)gB1h;
    rb0l = *(const uint4*)gB0l;  rb1l = *(const uint4*)gB1l;
    {
        char* d = sm;
        *(uint4*)(d + sa0) = ra0h;            *(uint4*)(d + sa1) = ra1h;
        *(uint4*)(d + OFF_ALO + sa0) = ra0l;  *(uint4*)(d + OFF_ALO + sa1) = ra1l;
        *(uint4*)(d + OFF_BHI + sb0) = rb0h;  *(uint4*)(d + OFF_BHI + sb1) = rb1h;
        *(uint4*)(d + OFF_BLO + sb0) = rb0l;  *(uint4*)(d + OFF_BLO + sb1) = rb1l;
    }
    __syncthreads();

    const int NIT = K >> 5;
    for (int it = 0; it < NIT; ++it) {
        if (it + 1 < NIT) {
            const int kq = (it + 1) << 5;
            const size_t bo = (size_t)kq * N;
            ra0h = *(const uint4*)(gA0h + kq);  ra1h = *(const uint4*)(gA1h + kq);
            ra0l = *(const uint4*)(gA0l + kq);  ra1l = *(const uint4*)(gA1l + kq);
            rb0h = *(const uint4*)(gB0h + bo);  rb1h = *(const uint4*)(gB1h + bo);
            rb0l = *(const uint4*)(gB0l + bo);  rb1l = *(const uint4*)(gB1l + bo);
        }

        const uint32_t base = sb + (uint32_t)((it & 1) * BUFSZ);
#pragma unroll
        for (int ks = 0; ks < 2; ++ks) {
            uint32_t ah[4][4], al[4][4], bh[2][4], bl[2][4];
            uint32_t aaddr = base + (uint32_t)((wm * 64 + (lane & 15)) * 80
                               + ks * 32 + ((lane >> 4) & 1) * 16);
#pragma unroll
            for (int mf = 0; mf < 4; ++mf) {
                ldm_x4(ah[mf], aaddr + mf * 1280);
                ldm_x4(al[mf], aaddr + OFF_ALO + mf * 1280);
            }
            uint32_t baddr = base + OFF_BHI
                + (uint32_t)((ks * 16 + (lane & 15)) * 272
                + (wn * 32 + ((lane >> 4) & 1) * 8) * 2);
#pragma unroll
            for (int np = 0; np < 2; ++np) {
                ldm_x4t(bh[np], baddr + np * 32);
                ldm_x4t(bl[np], baddr + (OFF_BLO - OFF_BHI) + np * 32);
            }
#pragma unroll
            for (int mf = 0; mf < 4; ++mf)
#pragma unroll
                for (int nf = 0; nf < 4; ++nf) {
                    const uint32_t* bhp = &bh[nf >> 1][(nf & 1) * 2];
                    const uint32_t* blp = &bl[nf >> 1][(nf & 1) * 2];
                    mma_bf16(acc[mf][nf], ah[mf], bhp);
                    mma_bf16(acc[mf][nf], ah[mf], blp);
                    mma_bf16(acc[mf][nf], al[mf], bhp);
                }
        }

        if (it + 1 < NIT) {
            char* d = sm + ((it + 1) & 1) * BUFSZ;
            *(uint4*)(d + sa0) = ra0h;            *(uint4*)(d + sa1) = ra1h;
            *(uint4*)(d + OFF_ALO + sa0) = ra0l;  *(uint4*)(d + OFF_ALO + sa1) = ra1l;
            *(uint4*)(d + OFF_BHI + sb0) = rb0h;  *(uint4*)(d + OFF_BHI + sb1) = rb1h;
            *(uint4*)(d + OFF_BLO + sb0) = rb0l;  *(uint4*)(d + OFF_BLO + sb1) = rb1l;
        }
        __syncthreads();
    }

    /* ---- epilogue ---- */
    const int row = m0 + wm * 64 + (lane >> 2);
    const int col = n0 + wn * 32 + (lane & 3) * 2;
#pragma unroll
    for (int nf = 0; nf < 4; ++nf) {
        const int c = col + nf * 8;
        float2 bv = make_float2(0.f, 0.f);
        if (ep) bv = *(const float2*)(bias + c);
#pragma unroll
        for (int mf = 0; mf < 4; ++mf) {
            const int r = row + mf * 16;
            float2 v0 = make_float2(acc[mf][nf][0] + bv.x, acc[mf][nf][1] + bv.y);
            float2 v1 = make_float2(acc[mf][nf][2] + bv.x, acc[mf][nf][3] + bv.y);
            if (ep == 1) {
                v0.x = fmaxf(v0.x, 0.f); v0.y = fmaxf(v0.y, 0.f);
                v1.x = fmaxf(v1.x, 0.f); v1.y = fmaxf(v1.y, 0.f);
            }
            *(float2*)(C + (size_t)r * N + c)       = v0;
            *(float2*)(C + (size_t)(r + 8) * N + c) = v1;
        }
    }
}

/* ================= SIMT GEMM (small shapes) ======================== */
__global__ __launch_bounds__(256)
void gemm_kernel(const float* __restrict__ A, int lda,
                 const float* __restrict__ B, int N, int K,
                 float* __restrict__ C,
                 const float* __restrict__ bias, int ep)
{
    __shared__ float As[16][68];
    __shared__ float Bs[16][68];

    const int tid  = threadIdx.x;
    const int tx   = tid & 15;
    const int ty   = tid >> 4;
    const int row0 = blockIdx.y * 64;
    const int col0 = blockIdx.x * 64;

    const int ar = tid >> 2;
    const int ak = (tid & 3) << 2;
    const int bk = tid >> 4;
    const int bn = (tid & 15) << 2;

    float acc[4][4];
#pragma unroll
    for (int i = 0; i < 4; ++i)
#pragma unroll
        for (int j = 0; j < 4; ++j) acc[i][j] = 0.f;

    for (int k0 = 0; k0 < K; k0 += 16) {
        float4 av = *(const float4*)(A + (size_t)(row0 + ar) * lda + k0 + ak);
        As[ak + 0][ar] = av.x;
        As[ak + 1][ar] = av.y;
        As[ak + 2][ar] = av.z;
        As[ak + 3][ar] = av.w;
        *(float4*)&Bs[bk][bn] =
            *(const float4*)(B + (size_t)(k0 + bk) * N + col0 + bn);
        __syncthreads();

#pragma unroll
        for (int kk = 0; kk < 16; ++kk) {
            float4 a = *(const float4*)&As[kk][ty << 2];
            float4 b = *(const float4*)&Bs[kk][tx << 2];
            float ai[4] = {a.x, a.y, a.z, a.w};
            float bj[4] = {b.x, b.y, b.z, b.w};
#pragma unroll
            for (int i = 0; i < 4; ++i)
#pragma unroll
                for (int j = 0; j < 4; ++j)
                    acc[i][j] = fmaf(ai[i], bj[j], acc[i][j]);
        }
        __syncthreads();
    }

    const int m0 = row0 + (ty << 2);
    const int n0 = col0 + (tx << 2);
    float4 bv = make_float4(0.f, 0.f, 0.f, 0.f);
    if (ep) bv = *(const float4*)(bias + n0);

#pragma unroll
    for (int i = 0; i < 4; ++i) {
        float4 o = make_float4(acc[i][0], acc[i][1], acc[i][2], acc[i][3]);
        if (ep == 3) {
            o.x = softplusf(o.x + bv.x); o.y = softplusf(o.y + bv.y);
            o.z = softplusf(o.z + bv.z); o.w = softplusf(o.w + bv.w);
        }
        *(float4*)(C + (size_t)(m0 + i) * N + n0) = o;
    }
}

/* ------------------------------------------------------------------ */
__global__ void flip_kernel(const float* __restrict__ x, float* __restrict__ xb)
{
    int idx = blockIdx.x * 256 + threadIdx.x;
    int c = idx & 127;
    int r = idx >> 7;
    int b = r >> 11;
    int l = r & 2047;
    ((float4*)xb)[idx] =
        ((const float4*)x)[(size_t)(((b << 11) + (2047 - l)) << 7) + c];
}

/* ------------------------------------------------------------------ */
__global__ void conv_silu_kernel(const float* __restrict__ xz,
                                 const float* __restrict__ cw,
                                 const float* __restrict__ cb,
                                 float* __restrict__ xc)
{
    int idx = blockIdx.x * blockDim.x + threadIdx.x;
    int e = idx & 1023;
    int r = idx >> 10;
    int l = r & 2047;
    int b = r >> 11;
    float s = cb[e];
#pragma unroll
    for (int k = 0; k < 4; ++k) {
        int ll = l + k - 3;
        if (ll >= 0)
            s = fmaf(xz[((size_t)((b << 11) + ll) << 11) + e], cw[(e << 2) + k], s);
    }
    xc[idx] = siluf(s);
}

/* ------------------------------------------------------------------ */
__global__ __launch_bounds__(256)
void scan_kernel(const float* __restrict__ delta, const float* __restrict__ xc,
                 const float* __restrict__ dbl,   const float* __restrict__ xz,
                 const float* __restrict__ A_log, const float* __restrict__ Dp,
                 float* __restrict__ y)
{
    int warp  = (blockIdx.x * blockDim.x + threadIdx.x) >> 5;
    int lane  = threadIdx.x & 31;
    int half  = lane >> 4;
    int n     = lane & 15;
    int chain = (warp << 1) + half;
    int b = chain >> 10;
    int e = chain & 1023;

    const float a  = -expf(A_log[(e << 4) + n]);
    const float dc = Dp[e];
    float h = 0.f;
    const int rowbase = b << 11;

    for (int l0 = 0; l0 < LL; l0 += 4) {
        float d[4], xv[4], bv[4], cv[4];
#pragma unroll
        for (int s = 0; s < 4; ++s) {
            int row = rowbase + l0 + s;
            d[s]  = __ldg(&delta[(size_t)(row << 10) + e]);
            xv[s] = __ldg(&xc   [(size_t)(row << 10) + e]);
            bv[s] = __ldg(&dbl  [(row << 6) + 32 + n]);
            cv[s] = __ldg(&dbl  [(row << 6) + 48 + n]);
        }
        float p[4];
#pragma unroll
        for (int s = 0; s < 4; ++s) {
            float dA = __expf(d[s] * a);
            h = fmaf(dA, h, d[s] * xv[s] * bv[s]);
            p[s] = h * cv[s];
        }
#pragma unroll
        for (int o = 1; o < 16; o <<= 1) {
#pragma unroll
            for (int s = 0; s < 4; ++s)
                p[s] += __shfl_xor_sync(0xffffffffu, p[s], o);
        }
        if (n == 0) {
#pragma unroll
            for (int s = 0; s < 4; ++s) {
                int row = rowbase + l0 + s;
                float zv = xz[((size_t)row << 11) + 1024 + e];
                y[(size_t)(row << 10) + e] = (p[s] + xv[s] * dc) * siluf(zv);
            }
        }
    }
}

/* ------------------------------------------------------------------ */
__global__ __launch_bounds__(128)
void ln_kernel(float* __restrict__ U, const float* __restrict__ g,
               const float* __restrict__ bb)
{
    int row = blockIdx.x;
    float4* p = (float4*)(U + (size_t)row * DM);
    int tid = threadIdx.x;
    int lane = tid & 31, w = tid >> 5;
    __shared__ float red[4];

    float4 v = p[tid];
    float s = v.x + v.y + v.z + v.w;
#pragma unroll
    for (int o = 16; o; o >>= 1) s += __shfl_xor_sync(0xffffffffu, s, o);
    if (!lane) red[w] = s;
    __syncthreads();
    float mu = (red[0] + red[1] + red[2] + red[3]) * (1.f / 512.f);

    float dx = v.x - mu, dy = v.y - mu, dz = v.z - mu, dw = v.w - mu;
    float s2 = dx*dx + dy*dy + dz*dz + dw*dw;
#pragma unroll
    for (int o = 16; o; o >>= 1) s2 += __shfl_xor_sync(0xffffffffu, s2, o);
    __syncthreads();
    if (!lane) red[w] = s2;
    __syncthreads();
    float var  = (red[0] + red[1] + red[2] + red[3]) * (1.f / 512.f);
    float rstd = rsqrtf(var + 1e-5f);

    int c = tid << 2;
    float4 go = *(const float4*)(g + c);
    float4 bo = *(const float4*)(bb + c);
    float4 o;
    o.x = dx * rstd * go.x + bo.x;
    o.y = dy * rstd * go.y + bo.y;
    o.z = dz * rstd * go.z + bo.z;
    o.w = dw * rstd * go.w + bo.w;
    p[tid] = o;
}

/* ------------------------------------------------------------------ */
__global__ void final_kernel(const float* __restrict__ V2,
                             const float* __restrict__ U,
                             float* __restrict__ out)
{
    int idx = blockIdx.x * 256 + threadIdx.x;
    const int off = (BLr * DM) >> 2;
    float4 a = ((const float4*)V2)[idx];
    float4 b = ((const float4*)V2)[idx + off];
    float4 c = ((const float4*)U)[idx];
    float4 d = ((const float4*)U)[idx + off];
    float4 o;
    o.x = a.x + b.x + c.x + d.x;
    o.y = a.y + b.y + c.y + d.y;
    o.z = a.z + b.z + c.z + d.z;
    o.w = a.w + b.w + c.w + d.w;
    ((float4*)out)[idx] = o;
}

/* ------------------------------------------------------------------ */
extern "C" void kernel_launch(void* const* d_in, const int* in_sizes, int n_in,
                              void* d_out, int out_size)
{
    (void)in_sizes; (void)n_in; (void)out_size;

    float *xb, *xz, *xc, *dbl, *delta, *y, *U, *Vh, *V2;
    __nv_bfloat16 *Ahi, *Alo, *Bhi, *Blo;
    cudaGetSymbolAddress((void**)&xb,    g_xb);
    cudaGetSymbolAddress((void**)&xz,    g_xz);
    cudaGetSymbolAddress((void**)&xc,    g_xc);
    cudaGetSymbolAddress((void**)&dbl,   g_dbl);
    cudaGetSymbolAddress((void**)&delta, g_delta);
    cudaGetSymbolAddress((void**)&y,     g_y);
    cudaGetSymbolAddress((void**)&U,     g_U);
    cudaGetSymbolAddress((void**)&Vh,    g_Vh);
    cudaGetSymbolAddress((void**)&V2,    g_V2);
    cudaGetSymbolAddress((void**)&Ahi,   g_Ahi);
    cudaGetSymbolAddress((void**)&Alo,   g_Alo);
    cudaGetSymbolAddress((void**)&Bhi,   g_Bhi);
    cudaGetSymbolAddress((void**)&Blo,   g_Blo);

    cudaFuncSetAttribute(mma_gemm, cudaFuncAttributeMaxDynamicSharedMemorySize,
                         MM_SMEM);

    const float* x = (const float*)d_in[0];
    const float* norm1_g = (const float*)d_in[19];
    const float* norm1_b = (const float*)d_in[20];
    const float* ffn_w1  = (const float*)d_in[23];
    const float* ffn_b1  = (const float*)d_in[24];
    const float* ffn_w2  = (const float*)d_in[25];
    const float* ffn_b2  = (const float*)d_in[26];

#define CVT(src, n) cvt_kernel<<<((n)/4 + 255)/256, 256>>>(src, Ahi, Alo, (n)/4)
#define CVTB(src, n) cvt_kernel<<<((n)/4 + 255)/256, 256>>>(src, Bhi, Blo, (n)/4)

    for (int dir = 0; dir < 2; ++dir) {
        const float* in_w    = (const float*)d_in[1 + dir * 9 + 0];
        const float* conv_w  = (const float*)d_in[1 + dir * 9 + 1];
        const float* conv_b  = (const float*)d_in[1 + dir * 9 + 2];
        const float* xproj_w = (const float*)d_in[1 + dir * 9 + 3];
        const float* dt_w    = (const float*)d_in[1 + dir * 9 + 4];
        const float* dt_b    = (const float*)d_in[1 + dir * 9 + 5];
        const float* A_log   = (const float*)d_in[1 + dir * 9 + 6];
        const float* Dv      = (const float*)d_in[1 + dir * 9 + 7];
        const float* out_w   = (const float*)d_in[1 + dir * 9 + 8];

        const float* Asrc = x;
        if (dir == 1) {
            flip_kernel<<<(BLr * DM / 4) / 256, 256>>>(x, xb);
            Asrc = xb;
        }

        /* xz = x @ in_w : 4096 x 2048 x 512 (HMMA) */
        CVT(Asrc, BLr * DM);
        CVTB(in_w, DM * 2 * ED_);
        mma_gemm<<<dim3(2 * ED_ / 128, BLr / 128), 256, MM_SMEM>>>(
            Ahi, Alo, Bhi, Blo, 2 * ED_, DM, xz, nullptr, 0);

        conv_silu_kernel<<<(BLr * ED_) / 256, 256>>>(xz, conv_w, conv_b, xc);

        /* dbl = xc @ xproj_w : 4096 x 64 x 1024 (SIMT) */
        gemm_kernel<<<dim3(1, BLr / 64), 256>>>(
            xc, ED_, xproj_w, 64, ED_, dbl, nullptr, 0);

        /* delta = softplus(dt @ dt_w + dt_b) : 4096 x 1024 x 32 (SIMT) */
        gemm_kernel<<<dim3(ED_ / 64, BLr / 64), 256>>>(
            dbl, 64, dt_w, ED_, DTR, delta, dt_b, 3);

        scan_kernel<<<128, 256>>>(delta, xc, dbl, xz, A_log, Dv, y);

        /* m = y @ out_w : 4096 x 512 x 1024 (HMMA) */
        CVT(y, BLr * ED_);
        CVTB(out_w, ED_ * DM);
        mma_gemm<<<dim3(DM / 128, BLr / 128), 256, MM_SMEM>>>(
            Ahi, Alo, Bhi, Blo, DM, ED_, U + (size_t)dir * BLr * DM, nullptr, 0);

        if (dir == 0)
            ln_kernel<<<BLr, 128>>>(U, norm1_g, norm1_b);
    }

    /* FFN batched over both directions: 8192 rows (HMMA) */
    CVT(U, 2 * BLr * DM);
    CVTB(ffn_w1, DM * DFF);
    mma_gemm<<<dim3(DFF / 128, 2 * BLr / 128), 256, MM_SMEM>>>(
        Ahi, Alo, Bhi, Blo, DFF, DM, Vh, ffn_b1, 1);

    CVT(Vh, 2 * BLr * DFF);
    CVTB(ffn_w2, DFF * DM);
    mma_gemm<<<dim3(DM / 128, 2 * BLr / 128), 256, MM_SMEM>>>(
        Ahi, Alo, Bhi, Blo, DM, DFF, V2, ffn_b2, 2);

    final_kernel<<<(BLr * DM / 4) / 256, 256>>>(V2, U, (float*)d_out);
}